// round 16
// baseline (speedup 1.0000x reference)
#include <cuda_runtime.h>
#include <cuda_bf16.h>
#include <math.h>
#include <stdint.h>

// Problem constants
#define BSZ  32
#define NTOK 320
#define CDIM 768
#define HN   12
#define STOK 256
#define TTOK 64
#define HD   64

typedef __nv_bfloat16 bf16;

// ---------------- scratch (__device__ globals: allocation-free) --------------
__device__ float g_tgt [BSZ * CDIM];
__device__ float g_tgtb[BSZ * 384];
__device__ float g_h1 [BSZ * STOK * 384];
__device__ float g_h2 [BSZ * STOK * 192];
__device__ int   g_grp[BSZ * NTOK];
__device__ float g_xsum[BSZ * CDIM];
__device__ float g_sumV[BSZ * HN * HD];

__device__ bf16  g_xhi [BSZ * NTOK * CDIM],      g_xlo [BSZ * NTOK * CDIM];
__device__ bf16  g_qwhi[3 * CDIM * CDIM],        g_qwlo[3 * CDIM * CDIM];
__device__ bf16  g_pwhi[CDIM * CDIM],            g_pwlo[CDIM * CDIM];
__device__ bf16  g_qkvhi[BSZ * NTOK * 3 * CDIM], g_qkvlo[BSZ * NTOK * 3 * CDIM];
__device__ bf16  g_aohi[BSZ * NTOK * CDIM],      g_aolo[BSZ * NTOK * CDIM];

__device__ __forceinline__ float gelu_exact(float v) {
    return 0.5f * v * (1.0f + erff(v * 0.70710678118654752f));
}

// ---------------- cp.async helpers -------------------------------------------
__device__ __forceinline__ void cpa16(void* s, const void* g) {
    unsigned sa = (unsigned)__cvta_generic_to_shared(s);
    asm volatile("cp.async.cg.shared.global [%0], [%1], 16;\n" :: "r"(sa), "l"(g));
}
__device__ __forceinline__ void cpa_commit() { asm volatile("cp.async.commit_group;\n"); }
template<int W> __device__ __forceinline__ void cpa_wait() {
    asm volatile("cp.async.wait_group %0;\n" :: "n"(W));
}

__device__ __forceinline__ void mma16816(float* c, const unsigned* a, const unsigned* b) {
    asm volatile(
        "mma.sync.aligned.m16n8k16.row.col.f32.bf16.bf16.f32 "
        "{%0,%1,%2,%3}, {%4,%5,%6,%7}, {%8,%9}, {%0,%1,%2,%3};\n"
        : "+f"(c[0]), "+f"(c[1]), "+f"(c[2]), "+f"(c[3])
        : "r"(a[0]), "r"(a[1]), "r"(a[2]), "r"(a[3]), "r"(b[0]), "r"(b[1]));
}

__device__ __forceinline__ void ldsm_x4(unsigned* r, unsigned saddr) {
    asm volatile("ldmatrix.sync.aligned.m8n8.x4.shared.b16 {%0,%1,%2,%3}, [%4];"
        : "=r"(r[0]), "=r"(r[1]), "=r"(r[2]), "=r"(r[3]) : "r"(saddr));
}
__device__ __forceinline__ void ldsm_x4_t(unsigned* r, unsigned saddr) {
    asm volatile("ldmatrix.sync.aligned.m8n8.x4.trans.shared.b16 {%0,%1,%2,%3}, [%4];"
        : "=r"(r[0]), "=r"(r[1]), "=r"(r[2]), "=r"(r[3]) : "r"(saddr));
}

__device__ __forceinline__ unsigned packbf2(float a, float b) {
    return (unsigned)__bfloat16_as_ushort(__float2bfloat16(a))
         | ((unsigned)__bfloat16_as_ushort(__float2bfloat16(b)) << 16);
}

// ================= pre-split bf16 hi/lo GEMM, cp.async + ldmatrix ============
template<int OUTMODE>
__global__ __launch_bounds__(256, 2)
void mma_bf16_kernel(const bf16* __restrict__ Ahi, const bf16* __restrict__ Alo,
                     const bf16* __restrict__ Bhi, const bf16* __restrict__ Blo,
                     const float* __restrict__ bias,
                     float* __restrict__ C, bf16* __restrict__ Chi, bf16* __restrict__ Clo,
                     int M, int N, int K, int lda, int ldb, int ldc,
                     float alpha)
{
    constexpr int ASZ  = 128 * 40;
    constexpr int BSZE = 128 * 40;

    extern __shared__ bf16 smem[];
    bf16* sA = smem;
    bf16* sB = smem + 4 * ASZ;
    const unsigned sAu = (unsigned)__cvta_generic_to_shared(sA);
    const unsigned sBu = (unsigned)__cvta_generic_to_shared(sB);

    const int t    = threadIdx.x;
    const int lane = t & 31;
    const int warp = t >> 5;
    const int wm   = warp >> 2;
    const int wn   = warp & 3;
    const int g    = lane >> 2;
    const int tg   = lane & 3;
    const int sel  = lane >> 3;
    const int m0   = blockIdx.y * 128;
    const int n0   = blockIdx.x * 128;

    float acc[4][4][4];
#pragma unroll
    for (int i = 0; i < 4; i++)
#pragma unroll
        for (int j = 0; j < 4; j++)
#pragma unroll
            for (int r = 0; r < 4; r++) acc[i][j][r] = 0.0f;

    auto loadStage = [&](int st, int k0) {
#pragma unroll
        for (int l = 0; l < 2; l++) {
            int idx = t + l * 256;
            int r   = idx >> 2;
            int kc  = (idx & 3) * 8;
            int rg  = m0 + r; if (rg > M - 1) rg = M - 1;
            long long go = (long long)rg * lda + k0 + kc;
            cpa16(sA + (st * 2 + 0) * ASZ + r * 40 + kc, Ahi + go);
            cpa16(sA + (st * 2 + 1) * ASZ + r * 40 + kc, Alo + go);
        }
#pragma unroll
        for (int l = 0; l < 2; l++) {
            int idx = t + l * 256;
            int r   = idx >> 2;
            int kc  = (idx & 3) * 8;
            int ng  = n0 + r; if (ng > N - 1) ng = N - 1;
            long long go = (long long)ng * ldb + k0 + kc;
            cpa16(sB + (st * 2 + 0) * BSZE + r * 40 + kc, Bhi + go);
            cpa16(sB + (st * 2 + 1) * BSZE + r * 40 + kc, Blo + go);
        }
        cpa_commit();
    };

    const int nslab = K / 32;
    loadStage(0, 0);

    const int arowoff = (sel & 1) * 8 + (lane & 7);
    const int acoloff = (sel >> 1) * 8;

    for (int ks = 0; ks < nslab; ks++) {
        const int st = ks & 1;
        if (ks + 1 < nslab) {
            loadStage(st ^ 1, (ks + 1) * 32);
            cpa_wait<1>();
        } else {
            cpa_wait<0>();
        }
        __syncthreads();

        const unsigned aHs = sAu + (unsigned)((st * 2 + 0) * ASZ) * 2;
        const unsigned aLs = sAu + (unsigned)((st * 2 + 1) * ASZ) * 2;
        const unsigned bHs = sBu + (unsigned)((st * 2 + 0) * BSZE) * 2;
        const unsigned bLs = sBu + (unsigned)((st * 2 + 1) * BSZE) * 2;

#pragma unroll
        for (int kh = 0; kh < 2; kh++) {
            unsigned ah[4][4], al[4][4];
#pragma unroll
            for (int mt = 0; mt < 4; mt++) {
                int ar = wm * 64 + mt * 16 + arowoff;
                int ac = kh * 16 + acoloff;
                unsigned off = (unsigned)(ar * 40 + ac) * 2;
                ldsm_x4(ah[mt], aHs + off);
                ldsm_x4(al[mt], aLs + off);
            }
            unsigned bhf[4][2], blf[4][2];
#pragma unroll
            for (int ntp = 0; ntp < 2; ntp++) {
                int nt = ntp * 2 + (sel >> 1);
                int br = wn * 32 + nt * 8 + (lane & 7);
                int bc = kh * 16 + (sel & 1) * 8;
                unsigned off = (unsigned)(br * 40 + bc) * 2;
                unsigned r4[4];
                ldsm_x4(r4, bHs + off);
                bhf[2 * ntp][0] = r4[0]; bhf[2 * ntp][1] = r4[1];
                bhf[2 * ntp + 1][0] = r4[2]; bhf[2 * ntp + 1][1] = r4[3];
                ldsm_x4(r4, bLs + off);
                blf[2 * ntp][0] = r4[0]; blf[2 * ntp][1] = r4[1];
                blf[2 * ntp + 1][0] = r4[2]; blf[2 * ntp + 1][1] = r4[3];
            }
#pragma unroll
            for (int mt = 0; mt < 4; mt++)
#pragma unroll
                for (int nt = 0; nt < 4; nt++) {
                    mma16816(acc[mt][nt], ah[mt], bhf[nt]);
                    mma16816(acc[mt][nt], al[mt], bhf[nt]);
                    mma16816(acc[mt][nt], ah[mt], blf[nt]);
                }
        }
        __syncthreads();
    }

#pragma unroll
    for (int mt = 0; mt < 4; mt++) {
        int m1 = m0 + wm * 64 + mt * 16 + g;
        int m2 = m1 + 8;
#pragma unroll
        for (int nt = 0; nt < 4; nt++) {
            int n1 = n0 + wn * 32 + nt * 8 + 2 * tg;
            float b0v = 0.f, b1v = 0.f;
            if (bias) {
                if (n1     < N) b0v = bias[n1];
                if (n1 + 1 < N) b1v = bias[n1 + 1];
            }
            const float* c = acc[mt][nt];
#pragma unroll
            for (int rr = 0; rr < 2; rr++) {
                int m = rr ? m2 : m1;
                if (m >= M) continue;
                float v0 = c[rr * 2 + 0] * alpha + b0v;
                float v1 = c[rr * 2 + 1] * alpha + b1v;
                long long base = (long long)m * ldc;
                if (OUTMODE == 0) {
                    if (n1     < N) C[base + n1    ] = v0;
                    if (n1 + 1 < N) C[base + n1 + 1] = v1;
                } else {
                    if (n1 < N) {
                        bf16 h = __float2bfloat16(v0);
                        Chi[base + n1] = h;
                        Clo[base + n1] = __float2bfloat16(v0 - __bfloat162float(h));
                    }
                    if (n1 + 1 < N) {
                        bf16 h = __float2bfloat16(v1);
                        Chi[base + n1 + 1] = h;
                        Clo[base + n1 + 1] = __float2bfloat16(v1 - __bfloat162float(h));
                    }
                }
            }
        }
    }
}

// ---------------- x token-sum per batch: g_xsum[b][c] = sum_j x[b][j][c] -----
__global__ void xsum_kernel(const float* __restrict__ x)
{
    int b = blockIdx.x;
    for (int c = threadIdx.x; c < CDIM; c += blockDim.x) {
        float s = 0.0f;
        const float* xb = x + (long long)b * NTOK * CDIM + c;
        for (int j = 0; j < NTOK; j++) s += xb[(long long)j * CDIM];
        g_xsum[b * CDIM + c] = s;
    }
}

// ---------------- sumV via algebra: sumV[b][n] = xsum[b].Wv[n] + 320*bv[n] ---
__global__ void sumvw_kernel(const float* __restrict__ qkv_w,
                             const float* __restrict__ qkv_b)
{
    const int warp = threadIdx.x >> 5;
    const int lane = threadIdx.x & 31;
    const int n = blockIdx.x * 8 + warp;             // 96 blocks x 8 warps = 768
    const float* wr = qkv_w + (long long)(2 * CDIM + n) * CDIM;
    float wreg[24];
#pragma unroll
    for (int i = 0; i < 24; i++) wreg[i] = wr[lane + i * 32];
    const float bn = (float)NTOK * qkv_b[2 * CDIM + n];
    for (int b = 0; b < BSZ; b++) {
        const float* xs = g_xsum + b * CDIM;
        float s = 0.0f;
#pragma unroll
        for (int i = 0; i < 24; i++) s += wreg[i] * xs[lane + i * 32];
#pragma unroll
        for (int o = 16; o > 0; o >>= 1) s += __shfl_xor_sync(0xffffffffu, s, o);
        if (lane == 0) g_sumV[b * CDIM + n] = s + bn;
    }
}

// ================= fused flash attention v4: 2 CTAs/SM, K/V double-buffered ==
#define QP 72
#define SQH 0
#define SQL (128 * QP)
#define STG0 (2 * 128 * QP)
#define STGSZ (4 * 64 * QP)
#define SMEM_ELEMS (2 * 128 * QP + 2 * STGSZ)
#define FLASH_SMEM (SMEM_ELEMS * 2 + 320 * 4)

__global__ __launch_bounds__(256, 2)
void flash_attn_kernel(int bhOff)
{
    extern __shared__ bf16 sm[];
    int* grp_s = (int*)(sm + SMEM_ELEMS);
    const unsigned smu = (unsigned)__cvta_generic_to_shared(sm);

    const int t  = threadIdx.x;
    const int qc = blockIdx.x;
    const int bh = blockIdx.y + bhOff;
    const int b  = bh / HN;
    const int h  = bh % HN;
    const int rows = (qc < 2) ? 128 : 64;

#pragma unroll
    for (int it = 0; it < 4; it++) {
        int idx = it * 256 + t;
        int r = idx >> 3, kc = (idx & 7) * 8;
        if (r < rows) {
            long long go = (long long)(b * NTOK + qc * 128 + r) * (3 * CDIM) + h * HD + kc;
            cpa16(sm + SQH + r * QP + kc, g_qkvhi + go);
            cpa16(sm + SQL + r * QP + kc, g_qkvlo + go);
        }
    }
    cpa_commit();
#pragma unroll
    for (int it = 0; it < 2; it++) {
        int tok = it * 256 + t;
        if (tok < NTOK) grp_s[tok] = g_grp[b * NTOK + tok];
    }

    auto loadKV = [&](int st, int c) {
        bf16* base = sm + STG0 + st * STGSZ;
#pragma unroll
        for (int it = 0; it < 3; it++) {
            int idx = it * 256 + t;
            int j = idx >> 3, kc = (idx & 7) * 8;
            if (j < 64) {
                long long gk = (long long)(b * NTOK + c * 64 + j) * (3 * CDIM) + CDIM + h * HD + kc;
                cpa16(base +               j * QP + kc, g_qkvhi + gk);
                cpa16(base +     64 * QP + j * QP + kc, g_qkvlo + gk);
                cpa16(base + 2 * 64 * QP + j * QP + kc, g_qkvhi + gk + CDIM);
                cpa16(base + 3 * 64 * QP + j * QP + kc, g_qkvlo + gk + CDIM);
            }
        }
        cpa_commit();
    };
    loadKV(0, 0);

    __syncthreads();

    const int lane = t & 31;
    const int w    = t >> 5;
    const int g    = lane >> 2;
    const int tg   = lane & 3;
    const int sel  = lane >> 3;
    const int r0   = w * 16;
    const bool act = (r0 < rows);
    const float epsn = 1e-6f / (float)NTOK;
    const int lmrow = (sel & 1) * 8 + (lane & 7);
    const int lmcol = (sel >> 1) * 8;
    const int qrow  = r0 + lmrow;

    const int i0  = qc * 128 + r0 + g;
    const int i1  = i0 + 8;
    const int gi0 = grp_s[act ? i0 : 0];
    const int gi1 = grp_s[act ? i1 : 0];

    float Oa[8][4];
#pragma unroll
    for (int i = 0; i < 8; i++)
#pragma unroll
        for (int r = 0; r < 4; r++) Oa[i][r] = 0.0f;
    float m0 = -3.4e38f, m1 = -3.4e38f, l0 = 0.0f, l1 = 0.0f;

    for (int c = 0; c < 5; c++) {
        const int st = c & 1;
        if (c < 4) {
            loadKV(st ^ 1, c + 1);
            cpa_wait<1>();
        } else {
            cpa_wait<0>();
        }
        __syncthreads();

        if (act) {
            const int j0g = c * 64;
            const unsigned kHs = smu + (unsigned)(STG0 + st * STGSZ) * 2;
            const unsigned kLs = kHs + (unsigned)(64 * QP) * 2;
            const unsigned vHs = kHs + (unsigned)(2 * 64 * QP) * 2;
            const unsigned vLs = kHs + (unsigned)(3 * 64 * QP) * 2;

            float Sa[8][4];
#pragma unroll
            for (int i = 0; i < 8; i++)
#pragma unroll
                for (int r = 0; r < 4; r++) Sa[i][r] = 0.0f;

#pragma unroll
            for (int kt = 0; kt < 4; kt++) {
                int qcc = kt * 16 + lmcol;
                unsigned qh4[4], ql4[4];
                ldsm_x4(qh4, smu + (unsigned)(SQH + qrow * QP + qcc) * 2);
                ldsm_x4(ql4, smu + (unsigned)(SQL + qrow * QP + qcc) * 2);
#pragma unroll
                for (int ntp = 0; ntp < 4; ntp++) {
                    int krow = (ntp * 2 + (sel >> 1)) * 8 + (lane & 7);
                    int kc   = kt * 16 + (sel & 1) * 8;
                    unsigned kh4[4], kl4[4];
                    ldsm_x4(kh4, kHs + (unsigned)(krow * QP + kc) * 2);
                    ldsm_x4(kl4, kLs + (unsigned)(krow * QP + kc) * 2);
                    mma16816(Sa[ntp * 2],     qh4, kh4);
                    mma16816(Sa[ntp * 2],     ql4, kh4);
                    mma16816(Sa[ntp * 2],     qh4, kl4);
                    mma16816(Sa[ntp * 2 + 1], qh4, kh4 + 2);
                    mma16816(Sa[ntp * 2 + 1], ql4, kh4 + 2);
                    mma16816(Sa[ntp * 2 + 1], qh4, kl4 + 2);
                }
            }

            float cm0 = -3.4e38f, cm1 = -3.4e38f;
#pragma unroll
            for (int nt = 0; nt < 8; nt++) {
#pragma unroll
                for (int r = 0; r < 4; r++) Sa[nt][r] *= 0.125f;
                cm0 = fmaxf(cm0, fmaxf(Sa[nt][0], Sa[nt][1]));
                cm1 = fmaxf(cm1, fmaxf(Sa[nt][2], Sa[nt][3]));
            }
            cm0 = fmaxf(cm0, __shfl_xor_sync(0xffffffffu, cm0, 1));
            cm0 = fmaxf(cm0, __shfl_xor_sync(0xffffffffu, cm0, 2));
            cm1 = fmaxf(cm1, __shfl_xor_sync(0xffffffffu, cm1, 1));
            cm1 = fmaxf(cm1, __shfl_xor_sync(0xffffffffu, cm1, 2));

            float mn0 = fmaxf(m0, cm0), mn1 = fmaxf(m1, cm1);
            float a0 = expf(m0 - mn0), a1 = expf(m1 - mn1);
#pragma unroll
            for (int nt = 0; nt < 8; nt++) {
                Oa[nt][0] *= a0; Oa[nt][1] *= a0;
                Oa[nt][2] *= a1; Oa[nt][3] *= a1;
            }
            l0 *= a0; l1 *= a1;

            float rs0 = 0.0f, rs1 = 0.0f;
#pragma unroll
            for (int nt = 0; nt < 8; nt++) {
                int j = j0g + nt * 8 + 2 * tg;
                int gj0 = grp_s[j], gj1 = grp_s[j + 1];
                bool ma = (gi0 == 2) | (gj0 == 2) | (gi0 == gj0);
                bool mb = (gi0 == 2) | (gj1 == 2) | (gi0 == gj1);
                bool mc = (gi1 == 2) | (gj0 == 2) | (gi1 == gj0);
                bool md = (gi1 == 2) | (gj1 == 2) | (gi1 == gj1);
                float e0 = ma ? expf(Sa[nt][0] - mn0) : 0.0f;
                float e1 = mb ? expf(Sa[nt][1] - mn0) : 0.0f;
                float e2 = mc ? expf(Sa[nt][2] - mn1) : 0.0f;
                float e3 = md ? expf(Sa[nt][3] - mn1) : 0.0f;
                Sa[nt][0] = e0; Sa[nt][1] = e1; Sa[nt][2] = e2; Sa[nt][3] = e3;
                rs0 += e0 + e1; rs1 += e2 + e3;
            }
            rs0 += __shfl_xor_sync(0xffffffffu, rs0, 1);
            rs0 += __shfl_xor_sync(0xffffffffu, rs0, 2);
            rs1 += __shfl_xor_sync(0xffffffffu, rs1, 1);
            rs1 += __shfl_xor_sync(0xffffffffu, rs1, 2);
            l0 += rs0; l1 += rs1;
            m0 = mn0; m1 = mn1;

#pragma unroll
            for (int kt = 0; kt < 4; kt++) {
                const float* cA = Sa[2 * kt];
                const float* cB = Sa[2 * kt + 1];
                unsigned ph[4], pl[4];
                {
                    bf16 h00 = __float2bfloat16(cA[0]), h01 = __float2bfloat16(cA[1]);
                    bf16 h02 = __float2bfloat16(cA[2]), h03 = __float2bfloat16(cA[3]);
                    bf16 h10 = __float2bfloat16(cB[0]), h11 = __float2bfloat16(cB[1]);
                    bf16 h12 = __float2bfloat16(cB[2]), h13 = __float2bfloat16(cB[3]);
                    ph[0] = (unsigned)__bfloat16_as_ushort(h00) | ((unsigned)__bfloat16_as_ushort(h01) << 16);
                    ph[1] = (unsigned)__bfloat16_as_ushort(h02) | ((unsigned)__bfloat16_as_ushort(h03) << 16);
                    ph[2] = (unsigned)__bfloat16_as_ushort(h10) | ((unsigned)__bfloat16_as_ushort(h11) << 16);
                    ph[3] = (unsigned)__bfloat16_as_ushort(h12) | ((unsigned)__bfloat16_as_ushort(h13) << 16);
                    pl[0] = packbf2(cA[0] - __bfloat162float(h00), cA[1] - __bfloat162float(h01));
                    pl[1] = packbf2(cA[2] - __bfloat162float(h02), cA[3] - __bfloat162float(h03));
                    pl[2] = packbf2(cB[0] - __bfloat162float(h10), cB[1] - __bfloat162float(h11));
                    pl[3] = packbf2(cB[2] - __bfloat162float(h12), cB[3] - __bfloat162float(h13));
                }
                const int vr = kt * 16 + lmrow;
#pragma unroll
                for (int np = 0; np < 4; np++) {
                    int vc = np * 16 + lmcol;
                    unsigned vh4[4], vl4[4];
                    ldsm_x4_t(vh4, vHs + (unsigned)(vr * QP + vc) * 2);
                    ldsm_x4_t(vl4, vLs + (unsigned)(vr * QP + vc) * 2);
                    mma16816(Oa[np * 2],     ph, vh4);
                    mma16816(Oa[np * 2],     pl, vh4);
                    mma16816(Oa[np * 2],     ph, vl4);
                    mma16816(Oa[np * 2 + 1], ph, vh4 + 2);
                    mma16816(Oa[np * 2 + 1], pl, vh4 + 2);
                    mma16816(Oa[np * 2 + 1], ph, vl4 + 2);
                }
            }
        }
        __syncthreads();
    }

    if (act) {
        const float inv0 = 1.0f / (l0 + 1e-6f);
        const float inv1 = 1.0f / (l1 + 1e-6f);
#pragma unroll
        for (int nt2 = 0; nt2 < 8; nt2++) {
            int dc = nt2 * 8 + 2 * tg;
            float sv0 = g_sumV[bh * HD + dc];
            float sv1 = g_sumV[bh * HD + dc + 1];
            {
                long long base = (long long)(b * NTOK + i0) * CDIM + h * HD + dc;
                float v0 = (Oa[nt2][0] + epsn * sv0) * inv0;
                float v1 = (Oa[nt2][1] + epsn * sv1) * inv0;
                bf16 h0 = __float2bfloat16(v0), h1 = __float2bfloat16(v1);
                g_aohi[base] = h0;     g_aolo[base]     = __float2bfloat16(v0 - __bfloat162float(h0));
                g_aohi[base + 1] = h1; g_aolo[base + 1] = __float2bfloat16(v1 - __bfloat162float(h1));
            }
            {
                long long base = (long long)(b * NTOK + i1) * CDIM + h * HD + dc;
                float v0 = (Oa[nt2][2] + epsn * sv0) * inv1;
                float v1 = (Oa[nt2][3] + epsn * sv1) * inv1;
                bf16 h0 = __float2bfloat16(v0), h1 = __float2bfloat16(v1);
                g_aohi[base] = h0;     g_aolo[base]     = __float2bfloat16(v0 - __bfloat162float(h0));
                g_aohi[base + 1] = h1; g_aolo[base + 1] = __float2bfloat16(v1 - __bfloat162float(h1));
            }
        }
    }
}

// ---------------- elementwise fp32 -> bf16 hi/lo split ------------------------
__global__ void split_kernel(const float* __restrict__ src,
                             bf16* __restrict__ hi, bf16* __restrict__ lo,
                             long long n4)
{
    long long i = (long long)blockIdx.x * blockDim.x + threadIdx.x;
    if (i >= n4) return;
    float4 v = ((const float4*)src)[i];
    float p[4] = {v.x, v.y, v.z, v.w};
    unsigned short hs[4], ls[4];
#pragma unroll
    for (int j = 0; j < 4; j++) {
        bf16 h = __float2bfloat16(p[j]);
        bf16 l = __float2bfloat16(p[j] - __bfloat162float(h));
        hs[j] = __bfloat16_as_ushort(h);
        ls[j] = __bfloat16_as_ushort(l);
    }
    ((uint2*)hi)[i] = make_uint2((unsigned)hs[0] | ((unsigned)hs[1] << 16),
                                 (unsigned)hs[2] | ((unsigned)hs[3] << 16));
    ((uint2*)lo)[i] = make_uint2((unsigned)ls[0] | ((unsigned)ls[1] << 16),
                                 (unsigned)ls[2] | ((unsigned)ls[3] << 16));
}

// ================= tf32x3 tensor GEMM (fp32-equivalent, decision path) =======
__device__ __forceinline__ unsigned f2tf32(float x) {
    unsigned r;
    asm("cvt.rna.tf32.f32 %0, %1;" : "=r"(r) : "f"(x));
    return r;
}
__device__ __forceinline__ void split_tf32(float x, unsigned& hi, unsigned& lo) {
    hi = f2tf32(x);
    lo = f2tf32(x - __uint_as_float(hi));
}
__device__ __forceinline__ void mma1688_tf32(float* c, const unsigned* a, const unsigned* b) {
    asm volatile(
        "mma.sync.aligned.m16n8k8.row.col.f32.tf32.tf32.f32 "
        "{%0,%1,%2,%3}, {%4,%5,%6,%7}, {%8,%9}, {%0,%1,%2,%3};\n"
        : "+f"(c[0]), "+f"(c[1]), "+f"(c[2]), "+f"(c[3])
        : "r"(a[0]), "r"(a[1]), "r"(a[2]), "r"(a[3]), "r"(b[0]), "r"(b[1]));
}

#define SPAD 132

__global__ __launch_bounds__(256, 2)
void mma_tf32_kernel(const float* __restrict__ A, const float* __restrict__ B,
                     const float* __restrict__ bias, float* __restrict__ C,
                     int M, int N, int K, int lda, int ldb, int ldc, int act,
                     long long aBatch, long long biasBatch, long long cBatch)
{
    const int z = blockIdx.z;
    A += (long long)z * aBatch;
    C += (long long)z * cBatch;
    if (bias) bias += (long long)z * biasBatch;

    __shared__ unsigned AsHi[16][SPAD], AsLo[16][SPAD];
    __shared__ unsigned BsHi[16][SPAD], BsLo[16][SPAD];

    const int t    = threadIdx.x;
    const int lane = t & 31;
    const int warp = t >> 5;
    const int wm   = warp >> 2;
    const int wn   = warp & 3;
    const int g    = lane >> 2;
    const int tg   = lane & 3;
    const int m0   = blockIdx.y * 128;
    const int n0   = blockIdx.x * 128;

    float acc[4][4][4];
#pragma unroll
    for (int i = 0; i < 4; i++)
#pragma unroll
        for (int j = 0; j < 4; j++)
#pragma unroll
            for (int r = 0; r < 4; r++) acc[i][j][r] = 0.0f;

    for (int k0 = 0; k0 < K; k0 += 16) {
#pragma unroll
        for (int l = 0; l < 2; l++) {
            int it  = t * 2 + l;
            int row = it >> 2;
            int f4  = it & 3;
            int m   = m0 + row;
            float4 v = make_float4(0.f, 0.f, 0.f, 0.f);
            if (m < M) v = *(const float4*)(A + (long long)m * lda + k0 + f4 * 4);
            const float* p = &v.x;
#pragma unroll
            for (int j = 0; j < 4; j++) {
                unsigned h, lo;
                split_tf32(p[j], h, lo);
                AsHi[f4 * 4 + j][row] = h;
                AsLo[f4 * 4 + j][row] = lo;
            }
        }
#pragma unroll
        for (int l = 0; l < 2; l++) {
            int it  = t * 2 + l;
            int row = it >> 2;
            int f4  = it & 3;
            int n   = n0 + row;
            float4 v = make_float4(0.f, 0.f, 0.f, 0.f);
            if (n < N) v = *(const float4*)(B + (long long)n * ldb + k0 + f4 * 4);
            const float* p = &v.x;
#pragma unroll
            for (int j = 0; j < 4; j++) {
                unsigned h, lo;
                split_tf32(p[j], h, lo);
                BsHi[f4 * 4 + j][row] = h;
                BsLo[f4 * 4 + j][row] = lo;
            }
        }
        __syncthreads();

#pragma unroll
        for (int ks = 0; ks < 2; ks++) {
            const int kb = ks * 8;
            unsigned ah[4][4], al[4][4];
#pragma unroll
            for (int mt = 0; mt < 4; mt++) {
                int mr = wm * 64 + mt * 16;
                ah[mt][0] = AsHi[kb + tg    ][mr + g    ];
                ah[mt][1] = AsHi[kb + tg    ][mr + g + 8];
                ah[mt][2] = AsHi[kb + tg + 4][mr + g    ];
                ah[mt][3] = AsHi[kb + tg + 4][mr + g + 8];
                al[mt][0] = AsLo[kb + tg    ][mr + g    ];
                al[mt][1] = AsLo[kb + tg    ][mr + g + 8];
                al[mt][2] = AsLo[kb + tg + 4][mr + g    ];
                al[mt][3] = AsLo[kb + tg + 4][mr + g + 8];
            }
            unsigned bh[4][2], bl[4][2];
#pragma unroll
            for (int nt = 0; nt < 4; nt++) {
                int nc = wn * 32 + nt * 8 + g;
                bh[nt][0] = BsHi[kb + tg    ][nc];
                bh[nt][1] = BsHi[kb + tg + 4][nc];
                bl[nt][0] = BsLo[kb + tg    ][nc];
                bl[nt][1] = BsLo[kb + tg + 4][nc];
            }
#pragma unroll
            for (int mt = 0; mt < 4; mt++)
#pragma unroll
                for (int nt = 0; nt < 4; nt++) {
                    mma1688_tf32(acc[mt][nt], ah[mt], bh[nt]);
                    mma1688_tf32(acc[mt][nt], al[mt], bh[nt]);
                    mma1688_tf32(acc[mt][nt], ah[mt], bl[nt]);
                }
        }
        __syncthreads();
    }

#pragma unroll
    for (int mt = 0; mt < 4; mt++) {
        int m1 = m0 + wm * 64 + mt * 16 + g;
        int m2 = m1 + 8;
#pragma unroll
        for (int nt = 0; nt < 4; nt++) {
            int n1 = n0 + wn * 32 + nt * 8 + 2 * tg;
            float b0v = 0.f, b1v = 0.f;
            if (bias) {
                if (n1     < N) b0v = bias[n1];
                if (n1 + 1 < N) b1v = bias[n1 + 1];
            }
            const float* c = acc[mt][nt];
            float v0, v1;
            if (m1 < M) {
                v0 = c[0] + b0v; v1 = c[1] + b1v;
                if (act == 1) { v0 = gelu_exact(v0); v1 = gelu_exact(v1); }
                if (n1     < N) C[(long long)m1 * ldc + n1    ] = v0;
                if (n1 + 1 < N) C[(long long)m1 * ldc + n1 + 1] = v1;
            }
            if (m2 < M) {
                v0 = c[2] + b0v; v1 = c[3] + b1v;
                if (act == 1) { v0 = gelu_exact(v0); v1 = gelu_exact(v1); }
                if (n1     < N) C[(long long)m2 * ldc + n1    ] = v0;
                if (n1 + 1 < N) C[(long long)m2 * ldc + n1 + 1] = v1;
            }
        }
    }
}

// ---------------- tgt_rep: masked mean over 64 template tokens ---------------
__global__ void tgt_kernel(const float* __restrict__ x, const float* __restrict__ mask)
{
    __shared__ float sMask[TTOK];
    int b = blockIdx.x;
    if (threadIdx.x < TTOK) sMask[threadIdx.x] = mask[b * TTOK + threadIdx.x];
    __syncthreads();
    for (int c = threadIdx.x; c < CDIM; c += blockDim.x) {
        float s = 0.0f;
        const float* xb = x + (long long)b * NTOK * CDIM + c;
#pragma unroll 8
        for (int t = 0; t < TTOK; t++) s += xb[(long long)t * CDIM] * sMask[t];
        g_tgt[b * CDIM + c] = s * (1.0f / (float)TTOK);
    }
}

// ---------------- per-batch MLP1 bias ----------------------------------------
__global__ void tgtb_kernel(const float* __restrict__ dp1_w,
                            const float* __restrict__ dp1_b)
{
    const int warp = threadIdx.x >> 5;
    const int lane = threadIdx.x & 31;
    const int n = blockIdx.x * 8 + warp;
    const float* wr = dp1_w + (long long)n * (2 * CDIM) + CDIM;
    float wreg[24];
#pragma unroll
    for (int i = 0; i < 24; i++) wreg[i] = wr[lane + i * 32];
    const float bn = dp1_b[n];
    for (int b = 0; b < BSZ; b++) {
        const float* tg = g_tgt + b * CDIM;
        float s = 0.0f;
#pragma unroll
        for (int i = 0; i < 24; i++) s += wreg[i] * tg[lane + i * 32];
#pragma unroll
        for (int o = 16; o > 0; o >>= 1) s += __shfl_xor_sync(0xffffffffu, s, o);
        if (lane == 0) g_tgtb[b * 384 + n] = s + bn;
    }
}

// ---------------- final MLP layer + argmax + groups + decision out -----------
__global__ void decide_kernel(const float* __restrict__ dp3_w,
                              const float* __restrict__ dp3_b,
                              float* dec_out)
{
    int idx = blockIdx.x * blockDim.x + threadIdx.x;
    if (idx >= BSZ * NTOK) return;
    int b = idx / NTOK, tok = idx % NTOK;
    if (tok < TTOK) { g_grp[idx] = 0; return; }
    int s = tok - TTOK;
    const float* h = g_h2 + ((long long)b * STOK + s) * 192;
    float l0 = dp3_b[0], l1 = dp3_b[1];
#pragma unroll 4
    for (int k = 0; k < 192; k++) {
        float hv = h[k];
        l0 += hv * dp3_w[k];
        l1 += hv * dp3_w[192 + k];
    }
    int cls = (l1 > l0) ? 1 : 0;
    g_grp[idx] = 1 + cls;
    if (dec_out) {
        long long o = ((long long)b * STOK + s) * 2;
        dec_out[o + 0] = (cls == 0) ? 1.0f : 0.0f;
        dec_out[o + 1] = (cls == 1) ? 1.0f : 0.0f;
    }
}

// ---------------- host launcher ----------------------------------------------
extern "C" void kernel_launch(void* const* d_in, const int* in_sizes, int n_in,
                              void* d_out, int out_size)
{
    const float* x      = (const float*)d_in[0];
    const float* tmask  = (const float*)d_in[1];
    const float* qkv_w  = (const float*)d_in[2];
    const float* qkv_b  = (const float*)d_in[3];
    const float* proj_w = (const float*)d_in[4];
    const float* proj_b = (const float*)d_in[5];
    const float* dp1_w  = (const float*)d_in[6];
    const float* dp1_b  = (const float*)d_in[7];
    const float* dp2_w  = (const float*)d_in[8];
    const float* dp2_b  = (const float*)d_in[9];
    const float* dp3_w  = (const float*)d_in[10];
    const float* dp3_b  = (const float*)d_in[11];
    float* out = (float*)d_out;

    const long long OUT_MAIN = (long long)BSZ * NTOK * CDIM;
    const long long OUT_DEC  = (long long)BSZ * STOK * 2;
    float* dec_out = ((long long)out_size >= OUT_MAIN + OUT_DEC) ? (out + OUT_MAIN) : nullptr;

    float *p_tgtb, *p_h1, *p_h2;
    bf16 *p_xhi, *p_xlo, *p_qwhi, *p_qwlo, *p_pwhi, *p_pwlo;
    bf16 *p_qkvhi, *p_qkvlo, *p_aohi, *p_aolo;
    cudaGetSymbolAddress((void**)&p_tgtb, g_tgtb);
    cudaGetSymbolAddress((void**)&p_h1,   g_h1);
    cudaGetSymbolAddress((void**)&p_h2,   g_h2);
    cudaGetSymbolAddress((void**)&p_xhi,  g_xhi);
    cudaGetSymbolAddress((void**)&p_xlo,  g_xlo);
    cudaGetSymbolAddress((void**)&p_qwhi, g_qwhi);
    cudaGetSymbolAddress((void**)&p_qwlo, g_qwlo);
    cudaGetSymbolAddress((void**)&p_pwhi, g_pwhi);
    cudaGetSymbolAddress((void**)&p_pwlo, g_pwlo);
    cudaGetSymbolAddress((void**)&p_qkvhi, g_qkvhi);
    cudaGetSymbolAddress((void**)&p_qkvlo, g_qkvlo);
    cudaGetSymbolAddress((void**)&p_aohi, g_aohi);
    cudaGetSymbolAddress((void**)&p_aolo, g_aolo);

    static cudaStream_t sB = nullptr, sC = nullptr;
    static cudaEvent_t evFork = nullptr, evJoin = nullptr, evF1 = nullptr,
                       evP1 = nullptr, evWS = nullptr;
    if (sB == nullptr) {
        cudaStreamCreateWithFlags(&sB, cudaStreamNonBlocking);
        cudaStreamCreateWithFlags(&sC, cudaStreamNonBlocking);
        cudaEventCreateWithFlags(&evFork, cudaEventDisableTiming);
        cudaEventCreateWithFlags(&evJoin, cudaEventDisableTiming);
        cudaEventCreateWithFlags(&evF1, cudaEventDisableTiming);
        cudaEventCreateWithFlags(&evP1, cudaEventDisableTiming);
        cudaEventCreateWithFlags(&evWS, cudaEventDisableTiming);
        cudaFuncSetAttribute(mma_bf16_kernel<2>,
                             cudaFuncAttributeMaxDynamicSharedMemorySize, 81920);
        cudaFuncSetAttribute(mma_bf16_kernel<0>,
                             cudaFuncAttributeMaxDynamicSharedMemorySize, 81920);
        cudaFuncSetAttribute(flash_attn_kernel,
                             cudaFuncAttributeMaxDynamicSharedMemorySize, FLASH_SMEM);
    }
    const int SMEM_A = 81920;

    // flash/proj split points: flash_A covers batches 0..23
    const int BH_A   = 24 * HN;                       // 288
    const int BH_B   = BSZ * HN - BH_A;               // 96
    const int MROWS1 = 24 * NTOK;                     // 7680 rows (b 0..23)
    const int MROWS2 = BSZ * NTOK - MROWS1;           // 2560 rows (b 24..31)
    const long long ROW1 = (long long)MROWS1 * CDIM;

    // -------- fork --------
    cudaEventRecord(evFork, 0);
    cudaStreamWaitEvent(sB, evFork, 0);
    cudaStreamWaitEvent(sC, evFork, 0);

    // sC: qkv_w split runs concurrent with main's x split
    split_kernel<<<(3 * CDIM * CDIM / 4 + 255) / 256, 256, 0, sC>>>(
        qkv_w, p_qwhi, p_qwlo, 3 * CDIM * CDIM / 4);
    cudaEventRecord(evWS, sC);

    // sB: decision-MLP chain + proj_w split + algebraic sumV (all hidden)
    split_kernel<<<(CDIM * CDIM / 4 + 255) / 256, 256, 0, sB>>>(
        proj_w, p_pwhi, p_pwlo, CDIM * CDIM / 4);
    xsum_kernel<<<BSZ, 256, 0, sB>>>(x);
    sumvw_kernel<<<96, 256, 0, sB>>>(qkv_w, qkv_b);
    tgt_kernel<<<BSZ, 256, 0, sB>>>(x, tmask);
    tgtb_kernel<<<48, 256, 0, sB>>>(dp1_w, dp1_b);
    mma_tf32_kernel<<<dim3(3, 2, BSZ), 256, 0, sB>>>(
        x + (long long)TTOK * CDIM, dp1_w, p_tgtb, p_h1,
        STOK, 384, CDIM,
        CDIM, 2 * CDIM, 384, 1,
        (long long)NTOK * CDIM, 384, (long long)STOK * 384);
    mma_tf32_kernel<<<dim3(2, (BSZ * STOK) / 128, 1), 256, 0, sB>>>(
        p_h1, dp2_w, dp2_b, p_h2,
        BSZ * STOK, 192, 384,
        384, 384, 192, 1,
        0, 0, 0);
    decide_kernel<<<(BSZ * NTOK + 255) / 256, 256, 0, sB>>>(dp3_w, dp3_b, dec_out);
    cudaEventRecord(evJoin, sB);

    // -------- main stream: x split (concurrent with qkv_w split on sC) ------
    split_kernel<<<(int)(((long long)BSZ * NTOK * CDIM / 4 + 255) / 256), 256>>>(
        x, p_xhi, p_xlo, (long long)BSZ * NTOK * CDIM / 4);
    cudaStreamWaitEvent(0, evWS, 0);

    // QKV GEMM: [10240,768] x [2304,768]^T -> qkv hi/lo
    mma_bf16_kernel<2><<<dim3(2304 / 128, (BSZ * NTOK) / 128), 256, SMEM_A>>>(
        p_xhi, p_xlo, p_qwhi, p_qwlo, qkv_b,
        nullptr, p_qkvhi, p_qkvlo,
        BSZ * NTOK, 3 * CDIM, CDIM,
        CDIM, CDIM, 3 * CDIM, 1.0f);

    // join: flash needs g_grp + g_sumV (both produced on sB)
    cudaStreamWaitEvent(0, evJoin, 0);

    // flash part A: batches 0..23, 2 CTAs/SM, K/V double-buffered
    flash_attn_kernel<<<dim3(3, BH_A), 256, FLASH_SMEM>>>(0);
    cudaEventRecord(evF1, 0);

    // proj part 1 (rows of b 0..23) on sC — overlaps flash part B
    cudaStreamWaitEvent(sC, evF1, 0);
    cudaStreamWaitEvent(sC, evJoin, 0);
    mma_bf16_kernel<0><<<dim3(CDIM / 128, MROWS1 / 128), 256, SMEM_A, sC>>>(
        p_aohi, p_aolo, p_pwhi, p_pwlo, proj_b,
        out, nullptr, nullptr,
        MROWS1, CDIM, CDIM,
        CDIM, CDIM, CDIM, 1.0f);
    cudaEventRecord(evP1, sC);

    // flash part B: batches 24..31
    flash_attn_kernel<<<dim3(3, BH_B), 256, FLASH_SMEM>>>(BH_A);

    // proj part 2 (rows of b 24..31) on main
    mma_bf16_kernel<0><<<dim3(CDIM / 128, MROWS2 / 128), 256, SMEM_A>>>(
        p_aohi + ROW1, p_aolo + ROW1, p_pwhi, p_pwlo, proj_b,
        out + ROW1, nullptr, nullptr,
        MROWS2, CDIM, CDIM,
        CDIM, CDIM, CDIM, 1.0f);

    // join sC so the graph's output is complete on stream 0
    cudaStreamWaitEvent(0, evP1, 0);
}

// round 17
// speedup vs baseline: 1.0435x; 1.0435x over previous
#include <cuda_runtime.h>
#include <cuda_bf16.h>
#include <math.h>
#include <stdint.h>

// Problem constants
#define BSZ  32
#define NTOK 320
#define CDIM 768
#define HN   12
#define STOK 256
#define TTOK 64
#define HD   64

typedef __nv_bfloat16 bf16;

// ---------------- scratch (__device__ globals: allocation-free) --------------
__device__ float g_tgt [BSZ * CDIM];
__device__ float g_tgtb[BSZ * 384];
__device__ float g_h1 [BSZ * STOK * 384];
__device__ float g_h2 [BSZ * STOK * 192];
__device__ int   g_grp[BSZ * NTOK];
__device__ float g_sumV[BSZ * HN * HD];

__device__ bf16  g_xhi [BSZ * NTOK * CDIM],      g_xlo [BSZ * NTOK * CDIM];
__device__ bf16  g_qwhi[3 * CDIM * CDIM],        g_qwlo[3 * CDIM * CDIM];
__device__ bf16  g_pwhi[CDIM * CDIM],            g_pwlo[CDIM * CDIM];
__device__ bf16  g_qkvhi[BSZ * NTOK * 3 * CDIM], g_qkvlo[BSZ * NTOK * 3 * CDIM];
__device__ bf16  g_aohi[BSZ * NTOK * CDIM],      g_aolo[BSZ * NTOK * CDIM];

__device__ __forceinline__ float gelu_exact(float v) {
    return 0.5f * v * (1.0f + erff(v * 0.70710678118654752f));
}

// ---------------- cp.async helpers -------------------------------------------
__device__ __forceinline__ void cpa16(void* s, const void* g) {
    unsigned sa = (unsigned)__cvta_generic_to_shared(s);
    asm volatile("cp.async.cg.shared.global [%0], [%1], 16;\n" :: "r"(sa), "l"(g));
}
__device__ __forceinline__ void cpa_commit() { asm volatile("cp.async.commit_group;\n"); }
template<int W> __device__ __forceinline__ void cpa_wait() {
    asm volatile("cp.async.wait_group %0;\n" :: "n"(W));
}

__device__ __forceinline__ void mma16816(float* c, const unsigned* a, const unsigned* b) {
    asm volatile(
        "mma.sync.aligned.m16n8k16.row.col.f32.bf16.bf16.f32 "
        "{%0,%1,%2,%3}, {%4,%5,%6,%7}, {%8,%9}, {%0,%1,%2,%3};\n"
        : "+f"(c[0]), "+f"(c[1]), "+f"(c[2]), "+f"(c[3])
        : "r"(a[0]), "r"(a[1]), "r"(a[2]), "r"(a[3]), "r"(b[0]), "r"(b[1]));
}

__device__ __forceinline__ void ldsm_x4(unsigned* r, unsigned saddr) {
    asm volatile("ldmatrix.sync.aligned.m8n8.x4.shared.b16 {%0,%1,%2,%3}, [%4];"
        : "=r"(r[0]), "=r"(r[1]), "=r"(r[2]), "=r"(r[3]) : "r"(saddr));
}
__device__ __forceinline__ void ldsm_x4_t(unsigned* r, unsigned saddr) {
    asm volatile("ldmatrix.sync.aligned.m8n8.x4.trans.shared.b16 {%0,%1,%2,%3}, [%4];"
        : "=r"(r[0]), "=r"(r[1]), "=r"(r[2]), "=r"(r[3]) : "r"(saddr));
}

__device__ __forceinline__ unsigned packbf2(float a, float b) {
    return (unsigned)__bfloat16_as_ushort(__float2bfloat16(a))
         | ((unsigned)__bfloat16_as_ushort(__float2bfloat16(b)) << 16);
}

// ================= pre-split bf16 hi/lo GEMM, cp.async + ldmatrix ============
template<int OUTMODE>
__global__ __launch_bounds__(256, 2)
void mma_bf16_kernel(const bf16* __restrict__ Ahi, const bf16* __restrict__ Alo,
                     const bf16* __restrict__ Bhi, const bf16* __restrict__ Blo,
                     const float* __restrict__ bias,
                     float* __restrict__ C, bf16* __restrict__ Chi, bf16* __restrict__ Clo,
                     int M, int N, int K, int lda, int ldb, int ldc,
                     float alpha)
{
    constexpr int ASZ  = 128 * 40;
    constexpr int BSZE = 128 * 40;

    extern __shared__ bf16 smem[];
    bf16* sA = smem;
    bf16* sB = smem + 4 * ASZ;
    const unsigned sAu = (unsigned)__cvta_generic_to_shared(sA);
    const unsigned sBu = (unsigned)__cvta_generic_to_shared(sB);

    const int t    = threadIdx.x;
    const int lane = t & 31;
    const int warp = t >> 5;
    const int wm   = warp >> 2;
    const int wn   = warp & 3;
    const int g    = lane >> 2;
    const int tg   = lane & 3;
    const int sel  = lane >> 3;
    const int m0   = blockIdx.y * 128;
    const int n0   = blockIdx.x * 128;

    float acc[4][4][4];
#pragma unroll
    for (int i = 0; i < 4; i++)
#pragma unroll
        for (int j = 0; j < 4; j++)
#pragma unroll
            for (int r = 0; r < 4; r++) acc[i][j][r] = 0.0f;

    auto loadStage = [&](int st, int k0) {
#pragma unroll
        for (int l = 0; l < 2; l++) {
            int idx = t + l * 256;
            int r   = idx >> 2;
            int kc  = (idx & 3) * 8;
            int rg  = m0 + r; if (rg > M - 1) rg = M - 1;
            long long go = (long long)rg * lda + k0 + kc;
            cpa16(sA + (st * 2 + 0) * ASZ + r * 40 + kc, Ahi + go);
            cpa16(sA + (st * 2 + 1) * ASZ + r * 40 + kc, Alo + go);
        }
#pragma unroll
        for (int l = 0; l < 2; l++) {
            int idx = t + l * 256;
            int r   = idx >> 2;
            int kc  = (idx & 3) * 8;
            int ng  = n0 + r; if (ng > N - 1) ng = N - 1;
            long long go = (long long)ng * ldb + k0 + kc;
            cpa16(sB + (st * 2 + 0) * BSZE + r * 40 + kc, Bhi + go);
            cpa16(sB + (st * 2 + 1) * BSZE + r * 40 + kc, Blo + go);
        }
        cpa_commit();
    };

    const int nslab = K / 32;
    loadStage(0, 0);

    const int arowoff = (sel & 1) * 8 + (lane & 7);
    const int acoloff = (sel >> 1) * 8;

    for (int ks = 0; ks < nslab; ks++) {
        const int st = ks & 1;
        if (ks + 1 < nslab) {
            loadStage(st ^ 1, (ks + 1) * 32);
            cpa_wait<1>();
        } else {
            cpa_wait<0>();
        }
        __syncthreads();

        const unsigned aHs = sAu + (unsigned)((st * 2 + 0) * ASZ) * 2;
        const unsigned aLs = sAu + (unsigned)((st * 2 + 1) * ASZ) * 2;
        const unsigned bHs = sBu + (unsigned)((st * 2 + 0) * BSZE) * 2;
        const unsigned bLs = sBu + (unsigned)((st * 2 + 1) * BSZE) * 2;

#pragma unroll
        for (int kh = 0; kh < 2; kh++) {
            unsigned ah[4][4], al[4][4];
#pragma unroll
            for (int mt = 0; mt < 4; mt++) {
                int ar = wm * 64 + mt * 16 + arowoff;
                int ac = kh * 16 + acoloff;
                unsigned off = (unsigned)(ar * 40 + ac) * 2;
                ldsm_x4(ah[mt], aHs + off);
                ldsm_x4(al[mt], aLs + off);
            }
            unsigned bhf[4][2], blf[4][2];
#pragma unroll
            for (int ntp = 0; ntp < 2; ntp++) {
                int nt = ntp * 2 + (sel >> 1);
                int br = wn * 32 + nt * 8 + (lane & 7);
                int bc = kh * 16 + (sel & 1) * 8;
                unsigned off = (unsigned)(br * 40 + bc) * 2;
                unsigned r4[4];
                ldsm_x4(r4, bHs + off);
                bhf[2 * ntp][0] = r4[0]; bhf[2 * ntp][1] = r4[1];
                bhf[2 * ntp + 1][0] = r4[2]; bhf[2 * ntp + 1][1] = r4[3];
                ldsm_x4(r4, bLs + off);
                blf[2 * ntp][0] = r4[0]; blf[2 * ntp][1] = r4[1];
                blf[2 * ntp + 1][0] = r4[2]; blf[2 * ntp + 1][1] = r4[3];
            }
#pragma unroll
            for (int mt = 0; mt < 4; mt++)
#pragma unroll
                for (int nt = 0; nt < 4; nt++) {
                    mma16816(acc[mt][nt], ah[mt], bhf[nt]);
                    mma16816(acc[mt][nt], al[mt], bhf[nt]);
                    mma16816(acc[mt][nt], ah[mt], blf[nt]);
                }
        }
        __syncthreads();
    }

#pragma unroll
    for (int mt = 0; mt < 4; mt++) {
        int m1 = m0 + wm * 64 + mt * 16 + g;
        int m2 = m1 + 8;
#pragma unroll
        for (int nt = 0; nt < 4; nt++) {
            int n1 = n0 + wn * 32 + nt * 8 + 2 * tg;
            float b0v = 0.f, b1v = 0.f;
            if (bias) {
                if (n1     < N) b0v = bias[n1];
                if (n1 + 1 < N) b1v = bias[n1 + 1];
            }
            const float* c = acc[mt][nt];
#pragma unroll
            for (int rr = 0; rr < 2; rr++) {
                int m = rr ? m2 : m1;
                if (m >= M) continue;
                float v0 = c[rr * 2 + 0] * alpha + b0v;
                float v1 = c[rr * 2 + 1] * alpha + b1v;
                long long base = (long long)m * ldc;
                if (OUTMODE == 0) {
                    if (n1     < N) C[base + n1    ] = v0;
                    if (n1 + 1 < N) C[base + n1 + 1] = v1;
                } else {
                    if (n1 < N) {
                        bf16 h = __float2bfloat16(v0);
                        Chi[base + n1] = h;
                        Clo[base + n1] = __float2bfloat16(v0 - __bfloat162float(h));
                    }
                    if (n1 + 1 < N) {
                        bf16 h = __float2bfloat16(v1);
                        Chi[base + n1 + 1] = h;
                        Clo[base + n1 + 1] = __float2bfloat16(v1 - __bfloat162float(h));
                    }
                }
            }
        }
    }
}

// ---------------- V column sums (bit-exact replica of old in-flash order) ----
__global__ void sumv_kernel()
{
    const int bh = blockIdx.x;
    const int d  = threadIdx.x;           // 0..63
    const int b  = bh / HN;
    const int h  = bh % HN;
    float p[4];
#pragma unroll
    for (int q = 0; q < 4; q++) {
        float s = 0.0f;
        for (int jj = 0; jj < 80; jj++) {
            int j = q * 80 + jj;
            long long go = (long long)(b * NTOK + j) * (3 * CDIM) + 2 * CDIM + h * HD + d;
            s += __bfloat162float(g_qkvhi[go]) + __bfloat162float(g_qkvlo[go]);
        }
        p[q] = s;
    }
    g_sumV[bh * HD + d] = ((p[0] + p[1]) + p[2]) + p[3];
}

// ================= fused flash attention v4: 2 CTAs/SM, K/V double-buffered ==
#define QP 72
#define SQH 0
#define SQL (128 * QP)
#define STG0 (2 * 128 * QP)
#define STGSZ (4 * 64 * QP)
#define SMEM_ELEMS (2 * 128 * QP + 2 * STGSZ)
#define FLASH_SMEM (SMEM_ELEMS * 2 + 320 * 4)

__global__ __launch_bounds__(256, 2)
void flash_attn_kernel(int bhOff)
{
    extern __shared__ bf16 sm[];
    int* grp_s = (int*)(sm + SMEM_ELEMS);
    const unsigned smu = (unsigned)__cvta_generic_to_shared(sm);

    const int t  = threadIdx.x;
    const int qc = blockIdx.x;
    const int bh = blockIdx.y + bhOff;
    const int b  = bh / HN;
    const int h  = bh % HN;
    const int rows = (qc < 2) ? 128 : 64;

#pragma unroll
    for (int it = 0; it < 4; it++) {
        int idx = it * 256 + t;
        int r = idx >> 3, kc = (idx & 7) * 8;
        if (r < rows) {
            long long go = (long long)(b * NTOK + qc * 128 + r) * (3 * CDIM) + h * HD + kc;
            cpa16(sm + SQH + r * QP + kc, g_qkvhi + go);
            cpa16(sm + SQL + r * QP + kc, g_qkvlo + go);
        }
    }
    cpa_commit();
#pragma unroll
    for (int it = 0; it < 2; it++) {
        int tok = it * 256 + t;
        if (tok < NTOK) grp_s[tok] = g_grp[b * NTOK + tok];
    }

    auto loadKV = [&](int st, int c) {
        bf16* base = sm + STG0 + st * STGSZ;
#pragma unroll
        for (int it = 0; it < 3; it++) {
            int idx = it * 256 + t;
            int j = idx >> 3, kc = (idx & 7) * 8;
            if (j < 64) {
                long long gk = (long long)(b * NTOK + c * 64 + j) * (3 * CDIM) + CDIM + h * HD + kc;
                cpa16(base +               j * QP + kc, g_qkvhi + gk);
                cpa16(base +     64 * QP + j * QP + kc, g_qkvlo + gk);
                cpa16(base + 2 * 64 * QP + j * QP + kc, g_qkvhi + gk + CDIM);
                cpa16(base + 3 * 64 * QP + j * QP + kc, g_qkvlo + gk + CDIM);
            }
        }
        cpa_commit();
    };
    loadKV(0, 0);

    __syncthreads();

    const int lane = t & 31;
    const int w    = t >> 5;
    const int g    = lane >> 2;
    const int tg   = lane & 3;
    const int sel  = lane >> 3;
    const int r0   = w * 16;
    const bool act = (r0 < rows);
    const float epsn = 1e-6f / (float)NTOK;
    const int lmrow = (sel & 1) * 8 + (lane & 7);
    const int lmcol = (sel >> 1) * 8;
    const int qrow  = r0 + lmrow;

    const int i0  = qc * 128 + r0 + g;
    const int i1  = i0 + 8;
    const int gi0 = grp_s[act ? i0 : 0];
    const int gi1 = grp_s[act ? i1 : 0];

    float Oa[8][4];
#pragma unroll
    for (int i = 0; i < 8; i++)
#pragma unroll
        for (int r = 0; r < 4; r++) Oa[i][r] = 0.0f;
    float m0 = -3.4e38f, m1 = -3.4e38f, l0 = 0.0f, l1 = 0.0f;

    for (int c = 0; c < 5; c++) {
        const int st = c & 1;
        if (c < 4) {
            loadKV(st ^ 1, c + 1);
            cpa_wait<1>();
        } else {
            cpa_wait<0>();
        }
        __syncthreads();

        if (act) {
            const int j0g = c * 64;
            const unsigned kHs = smu + (unsigned)(STG0 + st * STGSZ) * 2;
            const unsigned kLs = kHs + (unsigned)(64 * QP) * 2;
            const unsigned vHs = kHs + (unsigned)(2 * 64 * QP) * 2;
            const unsigned vLs = kHs + (unsigned)(3 * 64 * QP) * 2;

            float Sa[8][4];
#pragma unroll
            for (int i = 0; i < 8; i++)
#pragma unroll
                for (int r = 0; r < 4; r++) Sa[i][r] = 0.0f;

#pragma unroll
            for (int kt = 0; kt < 4; kt++) {
                int qcc = kt * 16 + lmcol;
                unsigned qh4[4], ql4[4];
                ldsm_x4(qh4, smu + (unsigned)(SQH + qrow * QP + qcc) * 2);
                ldsm_x4(ql4, smu + (unsigned)(SQL + qrow * QP + qcc) * 2);
#pragma unroll
                for (int ntp = 0; ntp < 4; ntp++) {
                    int krow = (ntp * 2 + (sel >> 1)) * 8 + (lane & 7);
                    int kc   = kt * 16 + (sel & 1) * 8;
                    unsigned kh4[4], kl4[4];
                    ldsm_x4(kh4, kHs + (unsigned)(krow * QP + kc) * 2);
                    ldsm_x4(kl4, kLs + (unsigned)(krow * QP + kc) * 2);
                    mma16816(Sa[ntp * 2],     qh4, kh4);
                    mma16816(Sa[ntp * 2],     ql4, kh4);
                    mma16816(Sa[ntp * 2],     qh4, kl4);
                    mma16816(Sa[ntp * 2 + 1], qh4, kh4 + 2);
                    mma16816(Sa[ntp * 2 + 1], ql4, kh4 + 2);
                    mma16816(Sa[ntp * 2 + 1], qh4, kl4 + 2);
                }
            }

            float cm0 = -3.4e38f, cm1 = -3.4e38f;
#pragma unroll
            for (int nt = 0; nt < 8; nt++) {
#pragma unroll
                for (int r = 0; r < 4; r++) Sa[nt][r] *= 0.125f;
                cm0 = fmaxf(cm0, fmaxf(Sa[nt][0], Sa[nt][1]));
                cm1 = fmaxf(cm1, fmaxf(Sa[nt][2], Sa[nt][3]));
            }
            cm0 = fmaxf(cm0, __shfl_xor_sync(0xffffffffu, cm0, 1));
            cm0 = fmaxf(cm0, __shfl_xor_sync(0xffffffffu, cm0, 2));
            cm1 = fmaxf(cm1, __shfl_xor_sync(0xffffffffu, cm1, 1));
            cm1 = fmaxf(cm1, __shfl_xor_sync(0xffffffffu, cm1, 2));

            float mn0 = fmaxf(m0, cm0), mn1 = fmaxf(m1, cm1);
            float a0 = expf(m0 - mn0), a1 = expf(m1 - mn1);
#pragma unroll
            for (int nt = 0; nt < 8; nt++) {
                Oa[nt][0] *= a0; Oa[nt][1] *= a0;
                Oa[nt][2] *= a1; Oa[nt][3] *= a1;
            }
            l0 *= a0; l1 *= a1;

            float rs0 = 0.0f, rs1 = 0.0f;
#pragma unroll
            for (int nt = 0; nt < 8; nt++) {
                int j = j0g + nt * 8 + 2 * tg;
                int gj0 = grp_s[j], gj1 = grp_s[j + 1];
                bool ma = (gi0 == 2) | (gj0 == 2) | (gi0 == gj0);
                bool mb = (gi0 == 2) | (gj1 == 2) | (gi0 == gj1);
                bool mc = (gi1 == 2) | (gj0 == 2) | (gi1 == gj0);
                bool md = (gi1 == 2) | (gj1 == 2) | (gi1 == gj1);
                float e0 = ma ? expf(Sa[nt][0] - mn0) : 0.0f;
                float e1 = mb ? expf(Sa[nt][1] - mn0) : 0.0f;
                float e2 = mc ? expf(Sa[nt][2] - mn1) : 0.0f;
                float e3 = md ? expf(Sa[nt][3] - mn1) : 0.0f;
                Sa[nt][0] = e0; Sa[nt][1] = e1; Sa[nt][2] = e2; Sa[nt][3] = e3;
                rs0 += e0 + e1; rs1 += e2 + e3;
            }
            rs0 += __shfl_xor_sync(0xffffffffu, rs0, 1);
            rs0 += __shfl_xor_sync(0xffffffffu, rs0, 2);
            rs1 += __shfl_xor_sync(0xffffffffu, rs1, 1);
            rs1 += __shfl_xor_sync(0xffffffffu, rs1, 2);
            l0 += rs0; l1 += rs1;
            m0 = mn0; m1 = mn1;

#pragma unroll
            for (int kt = 0; kt < 4; kt++) {
                const float* cA = Sa[2 * kt];
                const float* cB = Sa[2 * kt + 1];
                unsigned ph[4], pl[4];
                {
                    bf16 h00 = __float2bfloat16(cA[0]), h01 = __float2bfloat16(cA[1]);
                    bf16 h02 = __float2bfloat16(cA[2]), h03 = __float2bfloat16(cA[3]);
                    bf16 h10 = __float2bfloat16(cB[0]), h11 = __float2bfloat16(cB[1]);
                    bf16 h12 = __float2bfloat16(cB[2]), h13 = __float2bfloat16(cB[3]);
                    ph[0] = (unsigned)__bfloat16_as_ushort(h00) | ((unsigned)__bfloat16_as_ushort(h01) << 16);
                    ph[1] = (unsigned)__bfloat16_as_ushort(h02) | ((unsigned)__bfloat16_as_ushort(h03) << 16);
                    ph[2] = (unsigned)__bfloat16_as_ushort(h10) | ((unsigned)__bfloat16_as_ushort(h11) << 16);
                    ph[3] = (unsigned)__bfloat16_as_ushort(h12) | ((unsigned)__bfloat16_as_ushort(h13) << 16);
                    pl[0] = packbf2(cA[0] - __bfloat162float(h00), cA[1] - __bfloat162float(h01));
                    pl[1] = packbf2(cA[2] - __bfloat162float(h02), cA[3] - __bfloat162float(h03));
                    pl[2] = packbf2(cB[0] - __bfloat162float(h10), cB[1] - __bfloat162float(h11));
                    pl[3] = packbf2(cB[2] - __bfloat162float(h12), cB[3] - __bfloat162float(h13));
                }
                const int vr = kt * 16 + lmrow;
#pragma unroll
                for (int np = 0; np < 4; np++) {
                    int vc = np * 16 + lmcol;
                    unsigned vh4[4], vl4[4];
                    ldsm_x4_t(vh4, vHs + (unsigned)(vr * QP + vc) * 2);
                    ldsm_x4_t(vl4, vLs + (unsigned)(vr * QP + vc) * 2);
                    mma16816(Oa[np * 2],     ph, vh4);
                    mma16816(Oa[np * 2],     pl, vh4);
                    mma16816(Oa[np * 2],     ph, vl4);
                    mma16816(Oa[np * 2 + 1], ph, vh4 + 2);
                    mma16816(Oa[np * 2 + 1], pl, vh4 + 2);
                    mma16816(Oa[np * 2 + 1], ph, vl4 + 2);
                }
            }
        }
        __syncthreads();
    }

    if (act) {
        const float inv0 = 1.0f / (l0 + 1e-6f);
        const float inv1 = 1.0f / (l1 + 1e-6f);
#pragma unroll
        for (int nt2 = 0; nt2 < 8; nt2++) {
            int dc = nt2 * 8 + 2 * tg;
            float sv0 = g_sumV[bh * HD + dc];
            float sv1 = g_sumV[bh * HD + dc + 1];
            {
                long long base = (long long)(b * NTOK + i0) * CDIM + h * HD + dc;
                float v0 = (Oa[nt2][0] + epsn * sv0) * inv0;
                float v1 = (Oa[nt2][1] + epsn * sv1) * inv0;
                bf16 h0 = __float2bfloat16(v0), h1 = __float2bfloat16(v1);
                g_aohi[base] = h0;     g_aolo[base]     = __float2bfloat16(v0 - __bfloat162float(h0));
                g_aohi[base + 1] = h1; g_aolo[base + 1] = __float2bfloat16(v1 - __bfloat162float(h1));
            }
            {
                long long base = (long long)(b * NTOK + i1) * CDIM + h * HD + dc;
                float v0 = (Oa[nt2][2] + epsn * sv0) * inv1;
                float v1 = (Oa[nt2][3] + epsn * sv1) * inv1;
                bf16 h0 = __float2bfloat16(v0), h1 = __float2bfloat16(v1);
                g_aohi[base] = h0;     g_aolo[base]     = __float2bfloat16(v0 - __bfloat162float(h0));
                g_aohi[base + 1] = h1; g_aolo[base + 1] = __float2bfloat16(v1 - __bfloat162float(h1));
            }
        }
    }
}

// ---------------- elementwise fp32 -> bf16 hi/lo split ------------------------
__global__ void split_kernel(const float* __restrict__ src,
                             bf16* __restrict__ hi, bf16* __restrict__ lo,
                             long long n4)
{
    long long i = (long long)blockIdx.x * blockDim.x + threadIdx.x;
    if (i >= n4) return;
    float4 v = ((const float4*)src)[i];
    float p[4] = {v.x, v.y, v.z, v.w};
    unsigned short hs[4], ls[4];
#pragma unroll
    for (int j = 0; j < 4; j++) {
        bf16 h = __float2bfloat16(p[j]);
        bf16 l = __float2bfloat16(p[j] - __bfloat162float(h));
        hs[j] = __bfloat16_as_ushort(h);
        ls[j] = __bfloat16_as_ushort(l);
    }
    ((uint2*)hi)[i] = make_uint2((unsigned)hs[0] | ((unsigned)hs[1] << 16),
                                 (unsigned)hs[2] | ((unsigned)hs[3] << 16));
    ((uint2*)lo)[i] = make_uint2((unsigned)ls[0] | ((unsigned)ls[1] << 16),
                                 (unsigned)ls[2] | ((unsigned)ls[3] << 16));
}

// ================= tf32x3 tensor GEMM (fp32-equivalent, decision path) =======
__device__ __forceinline__ unsigned f2tf32(float x) {
    unsigned r;
    asm("cvt.rna.tf32.f32 %0, %1;" : "=r"(r) : "f"(x));
    return r;
}
__device__ __forceinline__ void split_tf32(float x, unsigned& hi, unsigned& lo) {
    hi = f2tf32(x);
    lo = f2tf32(x - __uint_as_float(hi));
}
__device__ __forceinline__ void mma1688_tf32(float* c, const unsigned* a, const unsigned* b) {
    asm volatile(
        "mma.sync.aligned.m16n8k8.row.col.f32.tf32.tf32.f32 "
        "{%0,%1,%2,%3}, {%4,%5,%6,%7}, {%8,%9}, {%0,%1,%2,%3};\n"
        : "+f"(c[0]), "+f"(c[1]), "+f"(c[2]), "+f"(c[3])
        : "r"(a[0]), "r"(a[1]), "r"(a[2]), "r"(a[3]), "r"(b[0]), "r"(b[1]));
}

#define SPAD 132

__global__ __launch_bounds__(256, 2)
void mma_tf32_kernel(const float* __restrict__ A, const float* __restrict__ B,
                     const float* __restrict__ bias, float* __restrict__ C,
                     int M, int N, int K, int lda, int ldb, int ldc, int act,
                     long long aBatch, long long biasBatch, long long cBatch)
{
    const int z = blockIdx.z;
    A += (long long)z * aBatch;
    C += (long long)z * cBatch;
    if (bias) bias += (long long)z * biasBatch;

    __shared__ unsigned AsHi[16][SPAD], AsLo[16][SPAD];
    __shared__ unsigned BsHi[16][SPAD], BsLo[16][SPAD];

    const int t    = threadIdx.x;
    const int lane = t & 31;
    const int warp = t >> 5;
    const int wm   = warp >> 2;
    const int wn   = warp & 3;
    const int g    = lane >> 2;
    const int tg   = lane & 3;
    const int m0   = blockIdx.y * 128;
    const int n0   = blockIdx.x * 128;

    float acc[4][4][4];
#pragma unroll
    for (int i = 0; i < 4; i++)
#pragma unroll
        for (int j = 0; j < 4; j++)
#pragma unroll
            for (int r = 0; r < 4; r++) acc[i][j][r] = 0.0f;

    for (int k0 = 0; k0 < K; k0 += 16) {
#pragma unroll
        for (int l = 0; l < 2; l++) {
            int it  = t * 2 + l;
            int row = it >> 2;
            int f4  = it & 3;
            int m   = m0 + row;
            float4 v = make_float4(0.f, 0.f, 0.f, 0.f);
            if (m < M) v = *(const float4*)(A + (long long)m * lda + k0 + f4 * 4);
            const float* p = &v.x;
#pragma unroll
            for (int j = 0; j < 4; j++) {
                unsigned h, lo;
                split_tf32(p[j], h, lo);
                AsHi[f4 * 4 + j][row] = h;
                AsLo[f4 * 4 + j][row] = lo;
            }
        }
#pragma unroll
        for (int l = 0; l < 2; l++) {
            int it  = t * 2 + l;
            int row = it >> 2;
            int f4  = it & 3;
            int n   = n0 + row;
            float4 v = make_float4(0.f, 0.f, 0.f, 0.f);
            if (n < N) v = *(const float4*)(B + (long long)n * ldb + k0 + f4 * 4);
            const float* p = &v.x;
#pragma unroll
            for (int j = 0; j < 4; j++) {
                unsigned h, lo;
                split_tf32(p[j], h, lo);
                BsHi[f4 * 4 + j][row] = h;
                BsLo[f4 * 4 + j][row] = lo;
            }
        }
        __syncthreads();

#pragma unroll
        for (int ks = 0; ks < 2; ks++) {
            const int kb = ks * 8;
            unsigned ah[4][4], al[4][4];
#pragma unroll
            for (int mt = 0; mt < 4; mt++) {
                int mr = wm * 64 + mt * 16;
                ah[mt][0] = AsHi[kb + tg    ][mr + g    ];
                ah[mt][1] = AsHi[kb + tg    ][mr + g + 8];
                ah[mt][2] = AsHi[kb + tg + 4][mr + g    ];
                ah[mt][3] = AsHi[kb + tg + 4][mr + g + 8];
                al[mt][0] = AsLo[kb + tg    ][mr + g    ];
                al[mt][1] = AsLo[kb + tg    ][mr + g + 8];
                al[mt][2] = AsLo[kb + tg + 4][mr + g    ];
                al[mt][3] = AsLo[kb + tg + 4][mr + g + 8];
            }
            unsigned bh[4][2], bl[4][2];
#pragma unroll
            for (int nt = 0; nt < 4; nt++) {
                int nc = wn * 32 + nt * 8 + g;
                bh[nt][0] = BsHi[kb + tg    ][nc];
                bh[nt][1] = BsHi[kb + tg + 4][nc];
                bl[nt][0] = BsLo[kb + tg    ][nc];
                bl[nt][1] = BsLo[kb + tg + 4][nc];
            }
#pragma unroll
            for (int mt = 0; mt < 4; mt++)
#pragma unroll
                for (int nt = 0; nt < 4; nt++) {
                    mma1688_tf32(acc[mt][nt], ah[mt], bh[nt]);
                    mma1688_tf32(acc[mt][nt], al[mt], bh[nt]);
                    mma1688_tf32(acc[mt][nt], ah[mt], bl[nt]);
                }
        }
        __syncthreads();
    }

#pragma unroll
    for (int mt = 0; mt < 4; mt++) {
        int m1 = m0 + wm * 64 + mt * 16 + g;
        int m2 = m1 + 8;
#pragma unroll
        for (int nt = 0; nt < 4; nt++) {
            int n1 = n0 + wn * 32 + nt * 8 + 2 * tg;
            float b0v = 0.f, b1v = 0.f;
            if (bias) {
                if (n1     < N) b0v = bias[n1];
                if (n1 + 1 < N) b1v = bias[n1 + 1];
            }
            const float* c = acc[mt][nt];
            float v0, v1;
            if (m1 < M) {
                v0 = c[0] + b0v; v1 = c[1] + b1v;
                if (act == 1) { v0 = gelu_exact(v0); v1 = gelu_exact(v1); }
                if (n1     < N) C[(long long)m1 * ldc + n1    ] = v0;
                if (n1 + 1 < N) C[(long long)m1 * ldc + n1 + 1] = v1;
            }
            if (m2 < M) {
                v0 = c[2] + b0v; v1 = c[3] + b1v;
                if (act == 1) { v0 = gelu_exact(v0); v1 = gelu_exact(v1); }
                if (n1     < N) C[(long long)m2 * ldc + n1    ] = v0;
                if (n1 + 1 < N) C[(long long)m2 * ldc + n1 + 1] = v1;
            }
        }
    }
}

// ---------------- tgt_rep: masked mean over 64 template tokens ---------------
__global__ void tgt_kernel(const float* __restrict__ x, const float* __restrict__ mask)
{
    __shared__ float sMask[TTOK];
    int b = blockIdx.x;
    if (threadIdx.x < TTOK) sMask[threadIdx.x] = mask[b * TTOK + threadIdx.x];
    __syncthreads();
    for (int c = threadIdx.x; c < CDIM; c += blockDim.x) {
        float s = 0.0f;
        const float* xb = x + (long long)b * NTOK * CDIM + c;
#pragma unroll 8
        for (int t = 0; t < TTOK; t++) s += xb[(long long)t * CDIM] * sMask[t];
        g_tgt[b * CDIM + c] = s * (1.0f / (float)TTOK);
    }
}

// ---------------- per-batch MLP1 bias ----------------------------------------
__global__ void tgtb_kernel(const float* __restrict__ dp1_w,
                            const float* __restrict__ dp1_b)
{
    const int warp = threadIdx.x >> 5;
    const int lane = threadIdx.x & 31;
    const int n = blockIdx.x * 8 + warp;
    const float* wr = dp1_w + (long long)n * (2 * CDIM) + CDIM;
    float wreg[24];
#pragma unroll
    for (int i = 0; i < 24; i++) wreg[i] = wr[lane + i * 32];
    const float bn = dp1_b[n];
    for (int b = 0; b < BSZ; b++) {
        const float* tg = g_tgt + b * CDIM;
        float s = 0.0f;
#pragma unroll
        for (int i = 0; i < 24; i++) s += wreg[i] * tg[lane + i * 32];
#pragma unroll
        for (int o = 16; o > 0; o >>= 1) s += __shfl_xor_sync(0xffffffffu, s, o);
        if (lane == 0) g_tgtb[b * 384 + n] = s + bn;
    }
}

// ---------------- final MLP layer + argmax + groups + decision out -----------
__global__ void decide_kernel(const float* __restrict__ dp3_w,
                              const float* __restrict__ dp3_b,
                              float* dec_out)
{
    int idx = blockIdx.x * blockDim.x + threadIdx.x;
    if (idx >= BSZ * NTOK) return;
    int b = idx / NTOK, tok = idx % NTOK;
    if (tok < TTOK) { g_grp[idx] = 0; return; }
    int s = tok - TTOK;
    const float* h = g_h2 + ((long long)b * STOK + s) * 192;
    float l0 = dp3_b[0], l1 = dp3_b[1];
#pragma unroll 4
    for (int k = 0; k < 192; k++) {
        float hv = h[k];
        l0 += hv * dp3_w[k];
        l1 += hv * dp3_w[192 + k];
    }
    int cls = (l1 > l0) ? 1 : 0;
    g_grp[idx] = 1 + cls;
    if (dec_out) {
        long long o = ((long long)b * STOK + s) * 2;
        dec_out[o + 0] = (cls == 0) ? 1.0f : 0.0f;
        dec_out[o + 1] = (cls == 1) ? 1.0f : 0.0f;
    }
}

// ---------------- host launcher ----------------------------------------------
extern "C" void kernel_launch(void* const* d_in, const int* in_sizes, int n_in,
                              void* d_out, int out_size)
{
    const float* x      = (const float*)d_in[0];
    const float* tmask  = (const float*)d_in[1];
    const float* qkv_w  = (const float*)d_in[2];
    const float* qkv_b  = (const float*)d_in[3];
    const float* proj_w = (const float*)d_in[4];
    const float* proj_b = (const float*)d_in[5];
    const float* dp1_w  = (const float*)d_in[6];
    const float* dp1_b  = (const float*)d_in[7];
    const float* dp2_w  = (const float*)d_in[8];
    const float* dp2_b  = (const float*)d_in[9];
    const float* dp3_w  = (const float*)d_in[10];
    const float* dp3_b  = (const float*)d_in[11];
    float* out = (float*)d_out;

    const long long OUT_MAIN = (long long)BSZ * NTOK * CDIM;
    const long long OUT_DEC  = (long long)BSZ * STOK * 2;
    float* dec_out = ((long long)out_size >= OUT_MAIN + OUT_DEC) ? (out + OUT_MAIN) : nullptr;

    float *p_tgtb, *p_h1, *p_h2;
    bf16 *p_xhi, *p_xlo, *p_qwhi, *p_qwlo, *p_pwhi, *p_pwlo;
    bf16 *p_qkvhi, *p_qkvlo, *p_aohi, *p_aolo;
    cudaGetSymbolAddress((void**)&p_tgtb, g_tgtb);
    cudaGetSymbolAddress((void**)&p_h1,   g_h1);
    cudaGetSymbolAddress((void**)&p_h2,   g_h2);
    cudaGetSymbolAddress((void**)&p_xhi,  g_xhi);
    cudaGetSymbolAddress((void**)&p_xlo,  g_xlo);
    cudaGetSymbolAddress((void**)&p_qwhi, g_qwhi);
    cudaGetSymbolAddress((void**)&p_qwlo, g_qwlo);
    cudaGetSymbolAddress((void**)&p_pwhi, g_pwhi);
    cudaGetSymbolAddress((void**)&p_pwlo, g_pwlo);
    cudaGetSymbolAddress((void**)&p_qkvhi, g_qkvhi);
    cudaGetSymbolAddress((void**)&p_qkvlo, g_qkvlo);
    cudaGetSymbolAddress((void**)&p_aohi, g_aohi);
    cudaGetSymbolAddress((void**)&p_aolo, g_aolo);

    static cudaStream_t sB = nullptr, sC = nullptr;
    static cudaEvent_t evFork = nullptr, evJoin = nullptr, evF1 = nullptr,
                       evP1 = nullptr, evWS = nullptr;
    if (sB == nullptr) {
        cudaStreamCreateWithFlags(&sB, cudaStreamNonBlocking);
        cudaStreamCreateWithFlags(&sC, cudaStreamNonBlocking);
        cudaEventCreateWithFlags(&evFork, cudaEventDisableTiming);
        cudaEventCreateWithFlags(&evJoin, cudaEventDisableTiming);
        cudaEventCreateWithFlags(&evF1, cudaEventDisableTiming);
        cudaEventCreateWithFlags(&evP1, cudaEventDisableTiming);
        cudaEventCreateWithFlags(&evWS, cudaEventDisableTiming);
        cudaFuncSetAttribute(mma_bf16_kernel<2>,
                             cudaFuncAttributeMaxDynamicSharedMemorySize, 81920);
        cudaFuncSetAttribute(mma_bf16_kernel<0>,
                             cudaFuncAttributeMaxDynamicSharedMemorySize, 81920);
        cudaFuncSetAttribute(flash_attn_kernel,
                             cudaFuncAttributeMaxDynamicSharedMemorySize, FLASH_SMEM);
    }
    const int SMEM_A = 81920;

    // flash/proj split points: flash_A covers batches 0..23
    const int BH_A   = 24 * HN;                       // 288
    const int BH_B   = BSZ * HN - BH_A;               // 96
    const int MROWS1 = 24 * NTOK;                     // 7680 rows (b 0..23)
    const int MROWS2 = BSZ * NTOK - MROWS1;           // 2560 rows (b 24..31)
    const long long ROW1 = (long long)MROWS1 * CDIM;

    // -------- fork --------
    cudaEventRecord(evFork, 0);
    cudaStreamWaitEvent(sB, evFork, 0);
    cudaStreamWaitEvent(sC, evFork, 0);

    // sC: qkv_w split runs concurrent with main's x split
    split_kernel<<<(3 * CDIM * CDIM / 4 + 255) / 256, 256, 0, sC>>>(
        qkv_w, p_qwhi, p_qwlo, 3 * CDIM * CDIM / 4);
    cudaEventRecord(evWS, sC);

    // sB: decision-MLP chain + proj_w split (hidden under main work)
    split_kernel<<<(CDIM * CDIM / 4 + 255) / 256, 256, 0, sB>>>(
        proj_w, p_pwhi, p_pwlo, CDIM * CDIM / 4);
    tgt_kernel<<<BSZ, 256, 0, sB>>>(x, tmask);
    tgtb_kernel<<<48, 256, 0, sB>>>(dp1_w, dp1_b);
    mma_tf32_kernel<<<dim3(3, 2, BSZ), 256, 0, sB>>>(
        x + (long long)TTOK * CDIM, dp1_w, p_tgtb, p_h1,
        STOK, 384, CDIM,
        CDIM, 2 * CDIM, 384, 1,
        (long long)NTOK * CDIM, 384, (long long)STOK * 384);
    mma_tf32_kernel<<<dim3(2, (BSZ * STOK) / 128, 1), 256, 0, sB>>>(
        p_h1, dp2_w, dp2_b, p_h2,
        BSZ * STOK, 192, 384,
        384, 384, 192, 1,
        0, 0, 0);
    decide_kernel<<<(BSZ * NTOK + 255) / 256, 256, 0, sB>>>(dp3_w, dp3_b, dec_out);
    cudaEventRecord(evJoin, sB);

    // -------- main stream: x split (concurrent with qkv_w split on sC) ------
    split_kernel<<<(int)(((long long)BSZ * NTOK * CDIM / 4 + 255) / 256), 256>>>(
        x, p_xhi, p_xlo, (long long)BSZ * NTOK * CDIM / 4);
    cudaStreamWaitEvent(0, evWS, 0);

    // QKV GEMM: [10240,768] x [2304,768]^T -> qkv hi/lo
    mma_bf16_kernel<2><<<dim3(2304 / 128, (BSZ * NTOK) / 128), 256, SMEM_A>>>(
        p_xhi, p_xlo, p_qwhi, p_qwlo, qkv_b,
        nullptr, p_qkvhi, p_qkvlo,
        BSZ * NTOK, 3 * CDIM, CDIM,
        CDIM, CDIM, 3 * CDIM, 1.0f);

    // V column sums (needed by flash epilogue; bit-exact R15 path)
    sumv_kernel<<<BSZ * HN, 64>>>();

    // join: flash needs g_grp (and proj needs pw splits, also on sB)
    cudaStreamWaitEvent(0, evJoin, 0);

    // flash part A: batches 0..23, 2 CTAs/SM, K/V double-buffered
    flash_attn_kernel<<<dim3(3, BH_A), 256, FLASH_SMEM>>>(0);
    cudaEventRecord(evF1, 0);

    // proj part 1 (rows of b 0..23) on sC — overlaps flash part B
    cudaStreamWaitEvent(sC, evF1, 0);
    cudaStreamWaitEvent(sC, evJoin, 0);
    mma_bf16_kernel<0><<<dim3(CDIM / 128, MROWS1 / 128), 256, SMEM_A, sC>>>(
        p_aohi, p_aolo, p_pwhi, p_pwlo, proj_b,
        out, nullptr, nullptr,
        MROWS1, CDIM, CDIM,
        CDIM, CDIM, CDIM, 1.0f);
    cudaEventRecord(evP1, sC);

    // flash part B: batches 24..31
    flash_attn_kernel<<<dim3(3, BH_B), 256, FLASH_SMEM>>>(BH_A);

    // proj part 2 (rows of b 24..31) on main
    mma_bf16_kernel<0><<<dim3(CDIM / 128, MROWS2 / 128), 256, SMEM_A>>>(
        p_aohi + ROW1, p_aolo + ROW1, p_pwhi, p_pwlo, proj_b,
        out + ROW1, nullptr, nullptr,
        MROWS2, CDIM, CDIM,
        CDIM, CDIM, CDIM, 1.0f);

    // join sC so the graph's output is complete on stream 0
    cudaStreamWaitEvent(0, evP1, 0);
}